// round 2
// baseline (speedup 1.0000x reference)
#include <cuda_runtime.h>

// Problem constants (match reference)
#define NN 200000
#define EE 6400000
#define FF 128
#define HH 16
#define CC 40
#define NBLK ((NN + 1023) / 1024)   // 196

// ---------------- device scratch (no allocations allowed) ----------------
__device__ int   g_is64;
__device__ int   g_src[EE];
__device__ int   g_dst[EE];
__device__ int   g_col[EE];
__device__ int   g_cnt[NN];
__device__ int   g_wp[NN];
__device__ int   g_rowptr[NN + 1];
__device__ int   g_tmp[NN];
__device__ int   g_bsums[NBLK];
__device__ float g_dis[NN];
__device__ float g_bufA[NN * HH];
__device__ float g_bufB[NN * HH];

// ---------------- preprocessing ----------------

// Detect whether edge_index is int64 or int32 (JAX x64-disabled silently
// downcasts jnp.int64 -> int32). Interpreting real int32 pairs as int64 gives
// values ~ lo + hi*2^32 which are out of [0, NN) almost surely.
__global__ void detect_k(const void* ei) {
    if (threadIdx.x == 0 && blockIdx.x == 0) {
        const long long* e64 = (const long long*)ei;
        int ok = 1;
        for (int i = 0; i < 64; i++) {
            long long v = e64[i];
            if (v < 0 || v >= NN) { ok = 0; break; }
        }
        g_is64 = ok;
    }
}

__global__ void zero_cnt_k() {
    int v = blockIdx.x * blockDim.x + threadIdx.x;
    if (v < NN) g_cnt[v] = 0;
}

// edge conversion (int64 or int32) + dst histogram
__global__ void prep_edges_k(const void* ei) {
    int e = blockIdx.x * blockDim.x + threadIdx.x;
    if (e >= EE) return;
    int s, d;
    if (g_is64) {
        const long long* p = (const long long*)ei;
        s = (int)p[e];
        d = (int)p[EE + e];
    } else {
        const int* p = (const int*)ei;
        s = p[e];
        d = p[EE + e];
    }
    // defensive clamp: any surprise fails rel_err instead of faulting
    s = min(max(s, 0), NN - 1);
    d = min(max(d, 0), NN - 1);
    g_src[e] = s;
    g_dst[e] = d;
    atomicAdd(&g_cnt[d], 1);
}

__global__ void dis_k() {
    int v = blockIdx.x * blockDim.x + threadIdx.x;
    if (v < NN) g_dis[v] = rsqrtf((float)(g_cnt[v] + 1));  // +1 self loop
}

// block-level inclusive scan of g_cnt
__global__ void scan1_k() {
    __shared__ int sh[1024];
    int i = blockIdx.x * 1024 + threadIdx.x;
    int v = (i < NN) ? g_cnt[i] : 0;
    sh[threadIdx.x] = v;
    __syncthreads();
    for (int off = 1; off < 1024; off <<= 1) {
        int t = (threadIdx.x >= off) ? sh[threadIdx.x - off] : 0;
        __syncthreads();
        sh[threadIdx.x] += t;
        __syncthreads();
    }
    if (i < NN) g_tmp[i] = sh[threadIdx.x];
    if (threadIdx.x == 1023) g_bsums[blockIdx.x] = sh[1023];
}

__global__ void scan2_k() {
    if (threadIdx.x == 0 && blockIdx.x == 0) {
        int running = 0;
        for (int i = 0; i < NBLK; i++) {
            int t = g_bsums[i];
            g_bsums[i] = running;
            running += t;
        }
    }
}

__global__ void scan3_k() {
    int i = blockIdx.x * blockDim.x + threadIdx.x;
    if (i >= NN) return;
    int incl = g_tmp[i] + g_bsums[i >> 10];
    g_rowptr[i + 1] = incl;
    g_wp[i] = incl - g_cnt[i];
    if (i == 0) g_rowptr[0] = 0;
}

__global__ void fill_k() {
    int e = blockIdx.x * blockDim.x + threadIdx.x;
    if (e >= EE) return;
    int d = g_dst[e];
    int p = atomicAdd(&g_wp[d], 1);
    g_col[p] = g_src[e];
}

// ---------------- compute layers ----------------
// t = dis * (x @ w_in)   : x [N,128] -> g_bufB [N,16]
__global__ void gemm_in_k(const float* __restrict__ x, const float* __restrict__ w) {
    __shared__ float sW[FF * HH];   // 8KB
    __shared__ float sX[16 * FF];   // 8KB
    int tid = threadIdx.x;          // 256
    for (int i = tid; i < FF * HH; i += 256) sW[i] = w[i];
    int base = blockIdx.x * 16;
    for (int i = tid; i < 16 * FF; i += 256) sX[i] = x[(long long)base * FF + i];
    __syncthreads();
    int r = tid >> 4, j = tid & 15;
    float acc = 0.f;
#pragma unroll
    for (int k = 0; k < FF; k++) acc += sX[r * FF + k] * sW[k * HH + j];
    int n = base + r;
    g_bufB[n * HH + j] = g_dis[n] * acc;
}

// t = dis * (h @ w)  : g_bufA [N,16] -> g_bufB [N,16]
__global__ void gemm_hid_k(const float* __restrict__ w) {
    __shared__ float sW[HH * HH];
    __shared__ float sH[16 * 17];
    int tid = threadIdx.x;  // 256
    sW[tid] = w[tid];
    int base = blockIdx.x * 16;
    sH[(tid >> 4) * 17 + (tid & 15)] = g_bufA[base * HH + tid];
    __syncthreads();
    int r = tid >> 4, j = tid & 15;
    float acc = 0.f;
#pragma unroll
    for (int k = 0; k < HH; k++) acc += sH[r * 17 + k] * sW[k * HH + j];
    int n = base + r;
    g_bufB[n * HH + j] = g_dis[n] * acc;
}

// t = dis * h (identity "gemm" for the last layer) : g_bufA -> g_bufB
__global__ void scale_k() {
    int i = blockIdx.x * blockDim.x + threadIdx.x;
    if (i < NN * HH) g_bufB[i] = g_bufA[i] * g_dis[i >> 4];
}

// h'[v] = act( dis[v] * (sum_{u->v} t[u] + t[v]) + b )   : g_bufB -> g_bufA
__global__ void agg_k(const float* __restrict__ bias, int do_relu) {
    int tid = blockIdx.x * blockDim.x + threadIdx.x;
    int v = tid >> 4;
    int f = tid & 15;
    if (v >= NN) return;
    int rs = g_rowptr[v];
    int re = g_rowptr[v + 1];
    const float* __restrict__ t = g_bufB;
    float acc = t[v * HH + f];  // self loop
    int e = rs;
    for (; e + 3 < re; e += 4) {
        int u0 = g_col[e];
        int u1 = g_col[e + 1];
        int u2 = g_col[e + 2];
        int u3 = g_col[e + 3];
        float a0 = t[u0 * HH + f];
        float a1 = t[u1 * HH + f];
        float a2 = t[u2 * HH + f];
        float a3 = t[u3 * HH + f];
        acc += (a0 + a1) + (a2 + a3);
    }
    for (; e < re; e++) acc += t[g_col[e] * HH + f];
    float val = g_dis[v] * acc + (bias ? bias[f] : 0.f);
    if (do_relu) val = fmaxf(val, 0.f);
    g_bufA[v * HH + f] = val;
}

// out = log_softmax( s @ w_out + b_out )  : g_bufA -> d_out [N,40]
__global__ void final_k(const float* __restrict__ wout, const float* __restrict__ bout,
                        float* __restrict__ out) {
    __shared__ float sW[HH * CC];
    __shared__ float sB[CC];
    int tid = threadIdx.x;  // 128
    for (int i = tid; i < HH * CC; i += blockDim.x) sW[i] = wout[i];
    if (tid < CC) sB[tid] = bout[tid];
    __syncthreads();
    int n = blockIdx.x * blockDim.x + tid;
    if (n >= NN) return;
    float s[HH];
#pragma unroll
    for (int k = 0; k < HH; k++) s[k] = g_bufA[n * HH + k];
    float l[CC];
    float m = -1e30f;
#pragma unroll
    for (int j = 0; j < CC; j++) {
        float a = sB[j];
#pragma unroll
        for (int k = 0; k < HH; k++) a += s[k] * sW[k * CC + j];
        l[j] = a;
        m = fmaxf(m, a);
    }
    float sum = 0.f;
#pragma unroll
    for (int j = 0; j < CC; j++) sum += __expf(l[j] - m);
    float lse = m + __logf(sum);
    float* o = out + (long long)n * CC;
#pragma unroll
    for (int j = 0; j < CC; j++) o[j] = l[j] - lse;
}

// ---------------- launch ----------------
extern "C" void kernel_launch(void* const* d_in, const int* in_sizes, int n_in,
                              void* d_out, int out_size) {
    const float* x      = (const float*)d_in[0];
    const float* w_in   = (const float*)d_in[1];
    const float* b_in   = (const float*)d_in[2];
    const float* w_hid  = (const float*)d_in[3];
    const float* b_hid  = (const float*)d_in[4];
    const float* w_out  = (const float*)d_in[5];
    const float* b_out  = (const float*)d_in[6];
    const void*  ei     = d_in[7];
    float* out = (float*)d_out;

    const int TB = 256;
    // preprocessing: dtype detect, degrees, dis, CSR by dst
    detect_k<<<1, 32>>>(ei);
    zero_cnt_k<<<(NN + TB - 1) / TB, TB>>>();
    prep_edges_k<<<(EE + TB - 1) / TB, TB>>>(ei);
    dis_k<<<(NN + TB - 1) / TB, TB>>>();
    scan1_k<<<NBLK, 1024>>>();
    scan2_k<<<1, 32>>>();
    scan3_k<<<(NN + TB - 1) / TB, TB>>>();
    fill_k<<<(EE + TB - 1) / TB, TB>>>();

    // layer 0: GEMM first (128 -> 16), then propagate 16 features
    gemm_in_k<<<NN / 16, 256>>>(x, w_in);
    agg_k<<<(NN * HH + TB - 1) / TB, TB>>>(b_in, 1);

    // 8 hidden layers
    for (int i = 0; i < 8; i++) {
        gemm_hid_k<<<NN / 16, 256>>>(w_hid + i * HH * HH);
        agg_k<<<(NN * HH + TB - 1) / TB, TB>>>(b_hid + i * HH, 1);
    }

    // last layer: propagate 16 features first, then (s @ W_out + b) + log_softmax
    scale_k<<<(NN * HH + TB - 1) / TB, TB>>>();
    agg_k<<<(NN * HH + TB - 1) / TB, TB>>>((const float*)nullptr, 0);
    final_k<<<(NN + 127) / 128, 128>>>(w_out, b_out, out);
}

// round 3
// speedup vs baseline: 1.3113x; 1.3113x over previous
#include <cuda_runtime.h>

// Problem constants (match reference)
#define NN 200000
#define EE 6400000
#define FF 128
#define HH 16
#define CC 40
#define NBLK ((NN + 1023) / 1024)   // 196

// ---------------- device scratch (no allocations allowed) ----------------
__device__ int    g_is64;
__device__ int    g_src[EE];
__device__ int    g_dst[EE];
__device__ int    g_col[EE];
__device__ int    g_cnt[NN];
__device__ int    g_wp[NN];
__device__ int    g_rowptr[NN + 1];
__device__ int    g_tmp[NN];
__device__ int    g_bsums[NBLK];
__device__ float  g_dis[NN];
__device__ float4 g_bufA4[NN * 4];   // [N,16] as float4 rows
__device__ float4 g_bufB4[NN * 4];

// ---------------- preprocessing ----------------

// Zero the degree histogram; thread 0 also detects edge_index dtype.
// (JAX with x64 disabled silently materializes jnp.int64 as int32; real int32
// pairs read as int64 give values far outside [0, NN).)
__global__ void detect_zero_k(const void* ei) {
    int v = blockIdx.x * blockDim.x + threadIdx.x;
    if (v < NN) g_cnt[v] = 0;
    if (v == 0) {
        const long long* e64 = (const long long*)ei;
        int ok = 1;
        for (int i = 0; i < 64; i++) {
            long long t = e64[i];
            if (t < 0 || t >= NN) { ok = 0; break; }
        }
        g_is64 = ok;
    }
}

// edge conversion (int64 or int32) + dst histogram
__global__ void prep_edges_k(const void* ei) {
    int e = blockIdx.x * blockDim.x + threadIdx.x;
    if (e >= EE) return;
    int s, d;
    if (g_is64) {
        const long long* p = (const long long*)ei;
        s = (int)p[e];
        d = (int)p[EE + e];
    } else {
        const int* p = (const int*)ei;
        s = p[e];
        d = p[EE + e];
    }
    s = min(max(s, 0), NN - 1);
    d = min(max(d, 0), NN - 1);
    g_src[e] = s;
    g_dst[e] = d;
    atomicAdd(&g_cnt[d], 1);
}

// block-level inclusive scan of g_cnt; also computes dis = rsqrt(deg+1)
__global__ void scan1_k() {
    __shared__ int sh[1024];
    int i = blockIdx.x * 1024 + threadIdx.x;
    int v = (i < NN) ? g_cnt[i] : 0;
    if (i < NN) g_dis[i] = rsqrtf((float)(v + 1));
    sh[threadIdx.x] = v;
    __syncthreads();
    for (int off = 1; off < 1024; off <<= 1) {
        int t = (threadIdx.x >= off) ? sh[threadIdx.x - off] : 0;
        __syncthreads();
        sh[threadIdx.x] += t;
        __syncthreads();
    }
    if (i < NN) g_tmp[i] = sh[threadIdx.x];
    if (threadIdx.x == 1023) g_bsums[blockIdx.x] = sh[1023];
}

__global__ void scan2_k() {
    if (threadIdx.x == 0 && blockIdx.x == 0) {
        int running = 0;
        for (int i = 0; i < NBLK; i++) {
            int t = g_bsums[i];
            g_bsums[i] = running;
            running += t;
        }
    }
}

__global__ void scan3_k() {
    int i = blockIdx.x * blockDim.x + threadIdx.x;
    if (i >= NN) return;
    int incl = g_tmp[i] + g_bsums[i >> 10];
    g_rowptr[i + 1] = incl;
    g_wp[i] = incl - g_cnt[i];
    if (i == 0) g_rowptr[0] = 0;
}

__global__ void fill_k() {
    int e = blockIdx.x * blockDim.x + threadIdx.x;
    if (e >= EE) return;
    int d = g_dst[e];
    int p = atomicAdd(&g_wp[d], 1);
    g_col[p] = g_src[e];
}

// ---------------- compute layers ----------------
// t1 = dis * (x @ w_in)   : x [N,128] -> g_bufB4 [N,16]
__global__ void gemm_in_k(const float* __restrict__ x, const float* __restrict__ w) {
    __shared__ float sW[FF * HH];   // 8KB
    __shared__ float sX[16 * FF];   // 8KB
    int tid = threadIdx.x;          // 256
    for (int i = tid; i < FF * HH; i += 256) sW[i] = w[i];
    int base = blockIdx.x * 16;
    for (int i = tid; i < 16 * FF; i += 256) sX[i] = x[(long long)base * FF + i];
    __syncthreads();
    int r = tid >> 4, j = tid & 15;
    float acc = 0.f;
#pragma unroll
    for (int k = 0; k < FF; k++) acc += sX[r * FF + k] * sW[k * HH + j];
    int n = base + r;
    ((float*)g_bufB4)[n * HH + j] = g_dis[n] * acc;
}

// Fused aggregation + epilogue.
//   acc = t[v] + sum_{u->v} t[u]                 (float4 per thread, 4 thr/node)
// MODE 0: h = relu(dis*acc + b);  t_next = dis*(h @ W16x16)   -> buffer
// MODE 1: h = relu(dis*acc + b);  t_next = dis*h               -> buffer
// MODE 2: s = dis*acc; logits = s @ Wout + bout; log_softmax   -> out [N,40]
template <int MODE>
__global__ void agg_fused_k(int dir, float* __restrict__ obuf,
                            const float* __restrict__ W, const float* __restrict__ B) {
    constexpr int WSZ = (MODE == 2) ? (HH * CC) : (HH * HH);
    constexpr int BSZ = (MODE == 2) ? CC : HH;
    __shared__ float sW[WSZ];
    __shared__ float sB[BSZ];
    int tid = threadIdx.x;  // 256 = 64 nodes * 4
    if (MODE == 0) {
        if (tid < WSZ) sW[tid] = W[tid];
    } else if (MODE == 2) {
        for (int i = tid; i < WSZ; i += 256) sW[i] = W[i];
    }
    if (tid < BSZ) sB[tid] = B[tid];
    __syncthreads();

    const float4* __restrict__ tin = dir ? g_bufB4 : g_bufA4;
    float4* __restrict__ tout = (MODE == 2) ? (float4*)obuf
                                            : (dir ? g_bufA4 : g_bufB4);

    int v = blockIdx.x * 64 + (tid >> 2);   // grid = 3125, exact
    int q = tid & 3;
    int rs = g_rowptr[v];
    int re = g_rowptr[v + 1];

    float4 acc = tin[v * 4 + q];  // self loop
    int e = rs;
    for (; e + 3 < re; e += 4) {
        int u0 = g_col[e], u1 = g_col[e + 1], u2 = g_col[e + 2], u3 = g_col[e + 3];
        float4 a0 = tin[u0 * 4 + q];
        float4 a1 = tin[u1 * 4 + q];
        float4 a2 = tin[u2 * 4 + q];
        float4 a3 = tin[u3 * 4 + q];
        acc.x += (a0.x + a1.x) + (a2.x + a3.x);
        acc.y += (a0.y + a1.y) + (a2.y + a3.y);
        acc.z += (a0.z + a1.z) + (a2.z + a3.z);
        acc.w += (a0.w + a1.w) + (a2.w + a3.w);
    }
    for (; e < re; e++) {
        float4 a = tin[g_col[e] * 4 + q];
        acc.x += a.x; acc.y += a.y; acc.z += a.z; acc.w += a.w;
    }
    float dv = g_dis[v];

    if (MODE == 0 || MODE == 1) {
        float hh[4];
        hh[0] = fmaxf(dv * acc.x + sB[4 * q + 0], 0.f);
        hh[1] = fmaxf(dv * acc.y + sB[4 * q + 1], 0.f);
        hh[2] = fmaxf(dv * acc.z + sB[4 * q + 2], 0.f);
        hh[3] = fmaxf(dv * acc.w + sB[4 * q + 3], 0.f);
        if (MODE == 1) {
            float4 o = make_float4(dv * hh[0], dv * hh[1], dv * hh[2], dv * hh[3]);
            tout[v * 4 + q] = o;
        } else {
            float t0 = 0.f, t1 = 0.f, t2 = 0.f, t3 = 0.f;
#pragma unroll
            for (int k = 0; k < 16; k++) {
                float hk = __shfl_sync(0xffffffffu, hh[k & 3], k >> 2, 4);
                const float* wr = &sW[k * 16 + 4 * q];
                t0 += hk * wr[0];
                t1 += hk * wr[1];
                t2 += hk * wr[2];
                t3 += hk * wr[3];
            }
            tout[v * 4 + q] = make_float4(dv * t0, dv * t1, dv * t2, dv * t3);
        }
    } else {
        // MODE 2: final layer + log_softmax
        float ss[4];
        ss[0] = dv * acc.x; ss[1] = dv * acc.y; ss[2] = dv * acc.z; ss[3] = dv * acc.w;
        float l[10];
#pragma unroll
        for (int j = 0; j < 10; j++) l[j] = sB[q * 10 + j];
#pragma unroll
        for (int k = 0; k < 16; k++) {
            float sk = __shfl_sync(0xffffffffu, ss[k & 3], k >> 2, 4);
            const float* wr = &sW[k * CC + q * 10];
#pragma unroll
            for (int j = 0; j < 10; j++) l[j] += sk * wr[j];
        }
        float m = l[0];
#pragma unroll
        for (int j = 1; j < 10; j++) m = fmaxf(m, l[j]);
        m = fmaxf(m, __shfl_xor_sync(0xffffffffu, m, 1, 4));
        m = fmaxf(m, __shfl_xor_sync(0xffffffffu, m, 2, 4));
        float sum = 0.f;
#pragma unroll
        for (int j = 0; j < 10; j++) sum += __expf(l[j] - m);
        sum += __shfl_xor_sync(0xffffffffu, sum, 1, 4);
        sum += __shfl_xor_sync(0xffffffffu, sum, 2, 4);
        float lse = m + __logf(sum);
        float2* o = (float2*)(obuf + (long long)v * CC + q * 10);
#pragma unroll
        for (int j = 0; j < 5; j++) o[j] = make_float2(l[2 * j] - lse, l[2 * j + 1] - lse);
    }
}

// ---------------- launch ----------------
extern "C" void kernel_launch(void* const* d_in, const int* in_sizes, int n_in,
                              void* d_out, int out_size) {
    const float* x      = (const float*)d_in[0];
    const float* w_in   = (const float*)d_in[1];
    const float* b_in   = (const float*)d_in[2];
    const float* w_hid  = (const float*)d_in[3];
    const float* b_hid  = (const float*)d_in[4];
    const float* w_out  = (const float*)d_in[5];
    const float* b_out  = (const float*)d_in[6];
    const void*  ei     = d_in[7];
    float* out = (float*)d_out;

    const int TB = 256;
    // preprocessing: dtype detect + zero, degrees, dis, CSR by dst
    detect_zero_k<<<(NN + TB - 1) / TB, TB>>>(ei);
    prep_edges_k<<<(EE + TB - 1) / TB, TB>>>(ei);
    scan1_k<<<NBLK, 1024>>>();
    scan2_k<<<1, 32>>>();
    scan3_k<<<(NN + TB - 1) / TB, TB>>>();
    fill_k<<<(EE + TB - 1) / TB, TB>>>();

    // layer 0 GEMM first (128 -> 16): t1 -> bufB  (dir=1 means input is B)
    gemm_in_k<<<NN / 16, 256>>>(x, w_in);

    // agg layers 1..8: fused relu + next-layer 16x16 GEMM
    for (int i = 1; i <= 8; i++) {
        int dir = (i & 1);  // odd: B->A, even: A->B
        const float* Wp = w_hid + (i - 1) * HH * HH;
        const float* Bp = (i == 1) ? b_in : (b_hid + (i - 2) * HH);
        agg_fused_k<0><<<NN / 64, 256>>>(dir, nullptr, Wp, Bp);
    }
    // agg layer 9: relu, t10 = dis*h  (in B, out A)
    agg_fused_k<1><<<NN / 64, 256>>>(1, nullptr, (const float*)nullptr, b_hid + 7 * HH);
    // agg layer 10: gather + W_out + log_softmax  (in A -> d_out)
    agg_fused_k<2><<<NN / 64, 256>>>(0, out, w_out, b_out);
}

// round 4
// speedup vs baseline: 1.3480x; 1.0280x over previous
#include <cuda_runtime.h>

// Problem constants (match reference)
#define NN 200000
#define EE 6400000
#define FF 128
#define HH 16
#define CC 40
#define NBLK ((NN + 1023) / 1024)   // 196

// ---------------- device scratch (no allocations allowed) ----------------
__device__ int    g_is64;
__device__ int    g_src[EE];
__device__ int    g_dst[EE];
__device__ int    g_col[EE];
__device__ int    g_cnt[NN];
__device__ int    g_wp[NN];
__device__ int    g_rowptr[NN + 1];
__device__ int    g_tmp[NN];
__device__ int    g_bsums[NBLK];
__device__ float  g_dis[NN];
__device__ float4 g_bufA4[NN * 4];   // [N,16] as float4 rows
__device__ float4 g_bufB4[NN * 4];

// ---------------- preprocessing ----------------

// Zero the degree histogram; thread 0 also detects edge_index dtype.
// (JAX with x64 disabled silently materializes jnp.int64 as int32; real int32
// pairs read as int64 give values far outside [0, NN).)
__global__ void detect_zero_k(const void* ei) {
    int v = blockIdx.x * blockDim.x + threadIdx.x;
    if (v < NN) g_cnt[v] = 0;
    if (v == 0) {
        const long long* e64 = (const long long*)ei;
        int ok = 1;
        for (int i = 0; i < 64; i++) {
            long long t = e64[i];
            if (t < 0 || t >= NN) { ok = 0; break; }
        }
        g_is64 = ok;
    }
}

__device__ __forceinline__ int clampN(int v) {
    return min(max(v, 0), NN - 1);
}

// edge conversion (int64 or int32) + dst histogram; 4 edges per thread
__global__ void prep_edges_k(const void* ei) {
    int t = blockIdx.x * blockDim.x + threadIdx.x;   // 0 .. EE/4-1
    if (t >= EE / 4) return;
    int s0, s1, s2, s3, d0, d1, d2, d3;
    if (g_is64) {
        const longlong2* p = (const longlong2*)ei;
        longlong2 a = p[t * 2], b = p[t * 2 + 1];
        longlong2 c = p[(EE / 2) + t * 2], d = p[(EE / 2) + t * 2 + 1];
        s0 = (int)a.x; s1 = (int)a.y; s2 = (int)b.x; s3 = (int)b.y;
        d0 = (int)c.x; d1 = (int)c.y; d2 = (int)d.x; d3 = (int)d.y;
    } else {
        const int4* p = (const int4*)ei;
        int4 a = p[t];
        int4 b = p[(EE / 4) + t];
        s0 = a.x; s1 = a.y; s2 = a.z; s3 = a.w;
        d0 = b.x; d1 = b.y; d2 = b.z; d3 = b.w;
    }
    s0 = clampN(s0); s1 = clampN(s1); s2 = clampN(s2); s3 = clampN(s3);
    d0 = clampN(d0); d1 = clampN(d1); d2 = clampN(d2); d3 = clampN(d3);
    ((int4*)g_src)[t] = make_int4(s0, s1, s2, s3);
    ((int4*)g_dst)[t] = make_int4(d0, d1, d2, d3);
    atomicAdd(&g_cnt[d0], 1);
    atomicAdd(&g_cnt[d1], 1);
    atomicAdd(&g_cnt[d2], 1);
    atomicAdd(&g_cnt[d3], 1);
}

// block-level inclusive scan of g_cnt; also computes dis = rsqrt(deg+1)
__global__ void scan1_k() {
    __shared__ int sh[1024];
    int i = blockIdx.x * 1024 + threadIdx.x;
    int v = (i < NN) ? g_cnt[i] : 0;
    if (i < NN) g_dis[i] = rsqrtf((float)(v + 1));
    sh[threadIdx.x] = v;
    __syncthreads();
    for (int off = 1; off < 1024; off <<= 1) {
        int t = (threadIdx.x >= off) ? sh[threadIdx.x - off] : 0;
        __syncthreads();
        sh[threadIdx.x] += t;
        __syncthreads();
    }
    if (i < NN) g_tmp[i] = sh[threadIdx.x];
    if (threadIdx.x == 1023) g_bsums[blockIdx.x] = sh[1023];
}

// parallel exclusive scan of the 196 block sums (one block)
__global__ void scan2_k() {
    __shared__ int sh[256];
    int i = threadIdx.x;
    int v = (i < NBLK) ? g_bsums[i] : 0;
    sh[i] = v;
    __syncthreads();
    for (int off = 1; off < 256; off <<= 1) {
        int t = (i >= off) ? sh[i - off] : 0;
        __syncthreads();
        sh[i] += t;
        __syncthreads();
    }
    if (i < NBLK) g_bsums[i] = sh[i] - v;   // exclusive
}

__global__ void scan3_k() {
    int i = blockIdx.x * blockDim.x + threadIdx.x;
    if (i >= NN) return;
    int incl = g_tmp[i] + g_bsums[i >> 10];
    g_rowptr[i + 1] = incl;
    g_wp[i] = incl - g_cnt[i];
    if (i == 0) g_rowptr[0] = 0;
}

// scatter src ids into CSR order; 4 edges per thread
__global__ void fill_k() {
    int t = blockIdx.x * blockDim.x + threadIdx.x;
    if (t >= EE / 4) return;
    int4 s = ((const int4*)g_src)[t];
    int4 d = ((const int4*)g_dst)[t];
    g_col[atomicAdd(&g_wp[d.x], 1)] = s.x;
    g_col[atomicAdd(&g_wp[d.y], 1)] = s.y;
    g_col[atomicAdd(&g_wp[d.z], 1)] = s.z;
    g_col[atomicAdd(&g_wp[d.w], 1)] = s.w;
}

// ---------------- compute layers ----------------
// t1 = dis * (x @ w_in)   : x [N,128] -> g_bufB4 [N,16]
__global__ void gemm_in_k(const float* __restrict__ x, const float* __restrict__ w) {
    __shared__ float sW[FF * HH];   // 8KB
    __shared__ float sX[16 * FF];   // 8KB
    int tid = threadIdx.x;          // 256
    {
        const float4* w4 = (const float4*)w;
        float4* sW4 = (float4*)sW;
        for (int i = tid; i < FF * HH / 4; i += 256) sW4[i] = w4[i];
        const float4* x4 = (const float4*)(x + (long long)blockIdx.x * 16 * FF);
        float4* sX4 = (float4*)sX;
        for (int i = tid; i < 16 * FF / 4; i += 256) sX4[i] = x4[i];
    }
    __syncthreads();
    int r = tid >> 4, j = tid & 15;
    float acc = 0.f;
#pragma unroll 16
    for (int k = 0; k < FF; k++) acc += sX[r * FF + k] * sW[k * HH + j];
    int n = blockIdx.x * 16 + r;
    ((float*)g_bufB4)[n * HH + j] = g_dis[n] * acc;
}

// Fused aggregation + epilogue.
//   acc = t[v] + sum_{u->v} t[u]                 (float4 per thread, 4 thr/node)
// MODE 0: h = relu(dis*acc + b);  t_next = dis*(h @ W16x16)   -> buffer
// MODE 1: h = relu(dis*acc + b);  t_next = dis*h               -> buffer
// MODE 2: s = dis*acc; logits = s @ Wout + bout; log_softmax   -> out [N,40]
template <int MODE>
__global__ void agg_fused_k(int dir, float* __restrict__ obuf,
                            const float* __restrict__ W, const float* __restrict__ B) {
    constexpr int WSZ = (MODE == 2) ? (HH * CC) : (HH * HH);
    constexpr int BSZ = (MODE == 2) ? CC : HH;
    __shared__ float sW[WSZ];
    __shared__ float sB[BSZ];
    int tid = threadIdx.x;  // 256 = 64 nodes * 4
    if (MODE == 0) {
        if (tid < WSZ) sW[tid] = W[tid];
    } else if (MODE == 2) {
        for (int i = tid; i < WSZ; i += 256) sW[i] = W[i];
    }
    if (tid < BSZ) sB[tid] = B[tid];
    __syncthreads();

    const float4* __restrict__ tin = dir ? g_bufB4 : g_bufA4;
    float4* __restrict__ tout = (MODE == 2) ? (float4*)obuf
                                            : (dir ? g_bufA4 : g_bufB4);

    int v = blockIdx.x * 64 + (tid >> 2);   // grid = 3125, exact
    int q = tid & 3;
    int rs = g_rowptr[v];
    int re = g_rowptr[v + 1];

    float4 acc = tin[v * 4 + q];  // self loop
    int e = rs;
    for (; e + 7 < re; e += 8) {
        int u0 = g_col[e],     u1 = g_col[e + 1], u2 = g_col[e + 2], u3 = g_col[e + 3];
        int u4 = g_col[e + 4], u5 = g_col[e + 5], u6 = g_col[e + 6], u7 = g_col[e + 7];
        float4 a0 = tin[u0 * 4 + q];
        float4 a1 = tin[u1 * 4 + q];
        float4 a2 = tin[u2 * 4 + q];
        float4 a3 = tin[u3 * 4 + q];
        float4 a4 = tin[u4 * 4 + q];
        float4 a5 = tin[u5 * 4 + q];
        float4 a6 = tin[u6 * 4 + q];
        float4 a7 = tin[u7 * 4 + q];
        acc.x += ((a0.x + a1.x) + (a2.x + a3.x)) + ((a4.x + a5.x) + (a6.x + a7.x));
        acc.y += ((a0.y + a1.y) + (a2.y + a3.y)) + ((a4.y + a5.y) + (a6.y + a7.y));
        acc.z += ((a0.z + a1.z) + (a2.z + a3.z)) + ((a4.z + a5.z) + (a6.z + a7.z));
        acc.w += ((a0.w + a1.w) + (a2.w + a3.w)) + ((a4.w + a5.w) + (a6.w + a7.w));
    }
    for (; e < re; e++) {
        float4 a = tin[g_col[e] * 4 + q];
        acc.x += a.x; acc.y += a.y; acc.z += a.z; acc.w += a.w;
    }
    float dv = g_dis[v];

    if (MODE == 0 || MODE == 1) {
        float hh[4];
        hh[0] = fmaxf(dv * acc.x + sB[4 * q + 0], 0.f);
        hh[1] = fmaxf(dv * acc.y + sB[4 * q + 1], 0.f);
        hh[2] = fmaxf(dv * acc.z + sB[4 * q + 2], 0.f);
        hh[3] = fmaxf(dv * acc.w + sB[4 * q + 3], 0.f);
        if (MODE == 1) {
            float4 o = make_float4(dv * hh[0], dv * hh[1], dv * hh[2], dv * hh[3]);
            tout[v * 4 + q] = o;
        } else {
            float t0 = 0.f, t1 = 0.f, t2 = 0.f, t3 = 0.f;
#pragma unroll
            for (int k = 0; k < 16; k++) {
                float hk = __shfl_sync(0xffffffffu, hh[k & 3], k >> 2, 4);
                const float* wr = &sW[k * 16 + 4 * q];
                t0 += hk * wr[0];
                t1 += hk * wr[1];
                t2 += hk * wr[2];
                t3 += hk * wr[3];
            }
            tout[v * 4 + q] = make_float4(dv * t0, dv * t1, dv * t2, dv * t3);
        }
    } else {
        // MODE 2: final layer + log_softmax
        float ss[4];
        ss[0] = dv * acc.x; ss[1] = dv * acc.y; ss[2] = dv * acc.z; ss[3] = dv * acc.w;
        float l[10];
#pragma unroll
        for (int j = 0; j < 10; j++) l[j] = sB[q * 10 + j];
#pragma unroll
        for (int k = 0; k < 16; k++) {
            float sk = __shfl_sync(0xffffffffu, ss[k & 3], k >> 2, 4);
            const float* wr = &sW[k * CC + q * 10];
#pragma unroll
            for (int j = 0; j < 10; j++) l[j] += sk * wr[j];
        }
        float m = l[0];
#pragma unroll
        for (int j = 1; j < 10; j++) m = fmaxf(m, l[j]);
        m = fmaxf(m, __shfl_xor_sync(0xffffffffu, m, 1, 4));
        m = fmaxf(m, __shfl_xor_sync(0xffffffffu, m, 2, 4));
        float sum = 0.f;
#pragma unroll
        for (int j = 0; j < 10; j++) sum += __expf(l[j] - m);
        sum += __shfl_xor_sync(0xffffffffu, sum, 1, 4);
        sum += __shfl_xor_sync(0xffffffffu, sum, 2, 4);
        float lse = m + __logf(sum);
        float2* o = (float2*)(obuf + (long long)v * CC + q * 10);
#pragma unroll
        for (int j = 0; j < 5; j++) o[j] = make_float2(l[2 * j] - lse, l[2 * j + 1] - lse);
    }
}

// ---------------- launch ----------------
extern "C" void kernel_launch(void* const* d_in, const int* in_sizes, int n_in,
                              void* d_out, int out_size) {
    const float* x      = (const float*)d_in[0];
    const float* w_in   = (const float*)d_in[1];
    const float* b_in   = (const float*)d_in[2];
    const float* w_hid  = (const float*)d_in[3];
    const float* b_hid  = (const float*)d_in[4];
    const float* w_out  = (const float*)d_in[5];
    const float* b_out  = (const float*)d_in[6];
    const void*  ei     = d_in[7];
    float* out = (float*)d_out;

    const int TB = 256;
    // preprocessing: dtype detect + zero, degrees, dis, CSR by dst
    detect_zero_k<<<(NN + TB - 1) / TB, TB>>>(ei);
    prep_edges_k<<<(EE / 4 + TB - 1) / TB, TB>>>(ei);
    scan1_k<<<NBLK, 1024>>>();
    scan2_k<<<1, 256>>>();
    scan3_k<<<(NN + TB - 1) / TB, TB>>>();
    fill_k<<<(EE / 4 + TB - 1) / TB, TB>>>();

    // layer 0 GEMM first (128 -> 16): t1 -> bufB  (dir=1 means input is B)
    gemm_in_k<<<NN / 16, 256>>>(x, w_in);

    // agg layers 1..8: fused relu + next-layer 16x16 GEMM
    for (int i = 1; i <= 8; i++) {
        int dir = (i & 1);  // odd: B->A, even: A->B
        const float* Wp = w_hid + (i - 1) * HH * HH;
        const float* Bp = (i == 1) ? b_in : (b_hid + (i - 2) * HH);
        agg_fused_k<0><<<NN / 64, 256>>>(dir, nullptr, Wp, Bp);
    }
    // agg layer 9: relu, t10 = dis*h  (in B, out A)
    agg_fused_k<1><<<NN / 64, 256>>>(1, nullptr, (const float*)nullptr, b_hid + 7 * HH);
    // agg layer 10: gather + W_out + log_softmax  (in A -> d_out)
    agg_fused_k<2><<<NN / 64, 256>>>(0, out, w_out, b_out);
}

// round 6
// speedup vs baseline: 1.3783x; 1.0225x over previous
#include <cuda_runtime.h>

// Problem constants (match reference)
#define NN 200000
#define EE 6400000
#define FF 128
#define HH 16
#define CC 40
#define NBLK ((NN + 1023) / 1024)   // 196

// ---------------- device scratch (no allocations allowed) ----------------
__device__ int    g_is64;
__device__ int    g_src[EE];
__device__ int    g_dst[EE];
__device__ int    g_col[EE];
__device__ int    g_cnt[NN];
__device__ int    g_wp[NN];
__device__ int    g_rowptr[NN + 1];
__device__ int    g_tmp[NN];
__device__ int    g_bsums[NBLK];
__device__ float  g_dis[NN];
__device__ float4 g_bufA4[NN * 4];   // [N,16] as float4 rows
__device__ float4 g_bufB4[NN * 4];

// ---------------- preprocessing ----------------

// Zero the degree histogram; thread 0 also detects edge_index dtype.
// (JAX with x64 disabled silently materializes jnp.int64 as int32; real int32
// pairs read as int64 give values far outside [0, NN).)
__global__ void detect_zero_k(const void* ei) {
    int v = blockIdx.x * blockDim.x + threadIdx.x;
    if (v < NN) g_cnt[v] = 0;
    if (v == 0) {
        const long long* e64 = (const long long*)ei;
        int ok = 1;
        for (int i = 0; i < 64; i++) {
            long long t = e64[i];
            if (t < 0 || t >= NN) { ok = 0; break; }
        }
        g_is64 = ok;
    }
}

__device__ __forceinline__ int clampN(int v) {
    return min(max(v, 0), NN - 1);
}

// edge conversion (int64 or int32) + dst histogram; 4 edges per thread
__global__ void prep_edges_k(const void* ei) {
    int t = blockIdx.x * blockDim.x + threadIdx.x;   // 0 .. EE/4-1
    if (t >= EE / 4) return;
    int s0, s1, s2, s3, d0, d1, d2, d3;
    if (g_is64) {
        const longlong2* p = (const longlong2*)ei;
        longlong2 a = p[t * 2], b = p[t * 2 + 1];
        longlong2 c = p[(EE / 2) + t * 2], d = p[(EE / 2) + t * 2 + 1];
        s0 = (int)a.x; s1 = (int)a.y; s2 = (int)b.x; s3 = (int)b.y;
        d0 = (int)c.x; d1 = (int)c.y; d2 = (int)d.x; d3 = (int)d.y;
    } else {
        const int4* p = (const int4*)ei;
        int4 a = p[t];
        int4 b = p[(EE / 4) + t];
        s0 = a.x; s1 = a.y; s2 = a.z; s3 = a.w;
        d0 = b.x; d1 = b.y; d2 = b.z; d3 = b.w;
    }
    s0 = clampN(s0); s1 = clampN(s1); s2 = clampN(s2); s3 = clampN(s3);
    d0 = clampN(d0); d1 = clampN(d1); d2 = clampN(d2); d3 = clampN(d3);
    ((int4*)g_src)[t] = make_int4(s0, s1, s2, s3);
    ((int4*)g_dst)[t] = make_int4(d0, d1, d2, d3);
    atomicAdd(&g_cnt[d0], 1);
    atomicAdd(&g_cnt[d1], 1);
    atomicAdd(&g_cnt[d2], 1);
    atomicAdd(&g_cnt[d3], 1);
}

// block-level inclusive scan of g_cnt; also computes dis = rsqrt(deg+1)
__global__ void scan1_k() {
    __shared__ int sh[1024];
    int i = blockIdx.x * 1024 + threadIdx.x;
    int v = (i < NN) ? g_cnt[i] : 0;
    if (i < NN) g_dis[i] = rsqrtf((float)(v + 1));
    sh[threadIdx.x] = v;
    __syncthreads();
    for (int off = 1; off < 1024; off <<= 1) {
        int t = (threadIdx.x >= off) ? sh[threadIdx.x - off] : 0;
        __syncthreads();
        sh[threadIdx.x] += t;
        __syncthreads();
    }
    if (i < NN) g_tmp[i] = sh[threadIdx.x];
    if (threadIdx.x == 1023) g_bsums[blockIdx.x] = sh[1023];
}

// parallel exclusive scan of the 196 block sums (one block)
__global__ void scan2_k() {
    __shared__ int sh[256];
    int i = threadIdx.x;
    int v = (i < NBLK) ? g_bsums[i] : 0;
    sh[i] = v;
    __syncthreads();
    for (int off = 1; off < 256; off <<= 1) {
        int t = (i >= off) ? sh[i - off] : 0;
        __syncthreads();
        sh[i] += t;
        __syncthreads();
    }
    if (i < NBLK) g_bsums[i] = sh[i] - v;   // exclusive
}

__global__ void scan3_k() {
    int i = blockIdx.x * blockDim.x + threadIdx.x;
    if (i >= NN) return;
    int incl = g_tmp[i] + g_bsums[i >> 10];
    g_rowptr[i + 1] = incl;
    g_wp[i] = incl - g_cnt[i];
    if (i == 0) g_rowptr[0] = 0;
}

// scatter src ids into CSR order; 4 edges per thread
__global__ void fill_k() {
    int t = blockIdx.x * blockDim.x + threadIdx.x;
    if (t >= EE / 4) return;
    int4 s = ((const int4*)g_src)[t];
    int4 d = ((const int4*)g_dst)[t];
    g_col[atomicAdd(&g_wp[d.x], 1)] = s.x;
    g_col[atomicAdd(&g_wp[d.y], 1)] = s.y;
    g_col[atomicAdd(&g_wp[d.z], 1)] = s.z;
    g_col[atomicAdd(&g_wp[d.w], 1)] = s.w;
}

// ---------------- compute layers ----------------
// t1 = dis * (x @ w_in)   : x [N,128] -> g_bufB4 [N,16]
__global__ void gemm_in_k(const float* __restrict__ x, const float* __restrict__ w) {
    __shared__ float sW[FF * HH];   // 8KB
    __shared__ float sX[16 * FF];   // 8KB
    int tid = threadIdx.x;          // 256
    {
        const float4* w4 = (const float4*)w;
        float4* sW4 = (float4*)sW;
        for (int i = tid; i < FF * HH / 4; i += 256) sW4[i] = w4[i];
        const float4* x4 = (const float4*)(x + (long long)blockIdx.x * 16 * FF);
        float4* sX4 = (float4*)sX;
        for (int i = tid; i < 16 * FF / 4; i += 256) sX4[i] = x4[i];
    }
    __syncthreads();
    int r = tid >> 4, j = tid & 15;
    float acc = 0.f;
#pragma unroll 16
    for (int k = 0; k < FF; k++) acc += sX[r * FF + k] * sW[k * HH + j];
    int n = blockIdx.x * 16 + r;
    ((float*)g_bufB4)[n * HH + j] = g_dis[n] * acc;
}

// Fused aggregation + epilogue.
//   acc = t[v] + sum_{u->v} t[u]                 (float4 per thread, 4 thr/node)
// MODE 0: h = relu(dis*acc + b);  t_next = dis*(h @ W16x16)   -> buffer
// MODE 1: h = relu(dis*acc + b);  t_next = dis*h               -> buffer
// MODE 2: s = dis*acc; logits = s @ Wout + bout; log_softmax   -> out [N,40]
template <int MODE>
__global__ void agg_fused_k(int dir, float* __restrict__ obuf,
                            const float* __restrict__ W, const float* __restrict__ B) {
    constexpr int WSZ = (MODE == 2) ? (HH * CC) : (HH * HH);
    constexpr int BSZ = (MODE == 2) ? CC : HH;
    __shared__ float sW[WSZ];
    __shared__ float sB[BSZ];
    int tid = threadIdx.x;  // 256 = 64 nodes * 4
    if (MODE == 0) {
        if (tid < WSZ) sW[tid] = W[tid];
    } else if (MODE == 2) {
        for (int i = tid; i < WSZ; i += 256) sW[i] = W[i];
    }
    if (tid < BSZ) sB[tid] = B[tid];
    __syncthreads();

    const float4* __restrict__ tin = dir ? g_bufB4 : g_bufA4;
    float4* __restrict__ tout = (MODE == 2) ? (float4*)obuf
                                            : (dir ? g_bufA4 : g_bufB4);

    int v = blockIdx.x * 64 + (tid >> 2);   // grid = 3125, exact
    int q = tid & 3;
    int rs = g_rowptr[v];
    int re = g_rowptr[v + 1];

    float4 acc = tin[v * 4 + q];  // self loop
    int e = rs;
    for (; e + 7 < re; e += 8) {
        int u0 = g_col[e],     u1 = g_col[e + 1], u2 = g_col[e + 2], u3 = g_col[e + 3];
        int u4 = g_col[e + 4], u5 = g_col[e + 5], u6 = g_col[e + 6], u7 = g_col[e + 7];
        float4 a0 = tin[u0 * 4 + q];
        float4 a1 = tin[u1 * 4 + q];
        float4 a2 = tin[u2 * 4 + q];
        float4 a3 = tin[u3 * 4 + q];
        float4 a4 = tin[u4 * 4 + q];
        float4 a5 = tin[u5 * 4 + q];
        float4 a6 = tin[u6 * 4 + q];
        float4 a7 = tin[u7 * 4 + q];
        acc.x += ((a0.x + a1.x) + (a2.x + a3.x)) + ((a4.x + a5.x) + (a6.x + a7.x));
        acc.y += ((a0.y + a1.y) + (a2.y + a3.y)) + ((a4.y + a5.y) + (a6.y + a7.y));
        acc.z += ((a0.z + a1.z) + (a2.z + a3.z)) + ((a4.z + a5.z) + (a6.z + a7.z));
        acc.w += ((a0.w + a1.w) + (a2.w + a3.w)) + ((a4.w + a5.w) + (a6.w + a7.w));
    }
    for (; e < re; e++) {
        float4 a = tin[g_col[e] * 4 + q];
        acc.x += a.x; acc.y += a.y; acc.z += a.z; acc.w += a.w;
    }
    float dv = g_dis[v];

    if (MODE == 0 || MODE == 1) {
        float hh[4];
        hh[0] = fmaxf(dv * acc.x + sB[4 * q + 0], 0.f);
        hh[1] = fmaxf(dv * acc.y + sB[4 * q + 1], 0.f);
        hh[2] = fmaxf(dv * acc.z + sB[4 * q + 2], 0.f);
        hh[3] = fmaxf(dv * acc.w + sB[4 * q + 3], 0.f);
        if (MODE == 1) {
            float4 o = make_float4(dv * hh[0], dv * hh[1], dv * hh[2], dv * hh[3]);
            tout[v * 4 + q] = o;
        } else {
            float t0 = 0.f, t1 = 0.f, t2 = 0.f, t3 = 0.f;
#pragma unroll
            for (int k = 0; k < 16; k++) {
                float hk = __shfl_sync(0xffffffffu, hh[k & 3], k >> 2, 4);
                const float* wr = &sW[k * 16 + 4 * q];
                t0 += hk * wr[0];
                t1 += hk * wr[1];
                t2 += hk * wr[2];
                t3 += hk * wr[3];
            }
            tout[v * 4 + q] = make_float4(dv * t0, dv * t1, dv * t2, dv * t3);
        }
    } else {
        // MODE 2: final layer + log_softmax
        float ss[4];
        ss[0] = dv * acc.x; ss[1] = dv * acc.y; ss[2] = dv * acc.z; ss[3] = dv * acc.w;
        float l[10];
#pragma unroll
        for (int j = 0; j < 10; j++) l[j] = sB[q * 10 + j];
#pragma unroll
        for (int k = 0; k < 16; k++) {
            float sk = __shfl_sync(0xffffffffu, ss[k & 3], k >> 2, 4);
            const float* wr = &sW[k * CC + q * 10];
#pragma unroll
            for (int j = 0; j < 10; j++) l[j] += sk * wr[j];
        }
        float m = l[0];
#pragma unroll
        for (int j = 1; j < 10; j++) m = fmaxf(m, l[j]);
        m = fmaxf(m, __shfl_xor_sync(0xffffffffu, m, 1, 4));
        m = fmaxf(m, __shfl_xor_sync(0xffffffffu, m, 2, 4));
        float sum = 0.f;
#pragma unroll
        for (int j = 0; j < 10; j++) sum += __expf(l[j] - m);
        sum += __shfl_xor_sync(0xffffffffu, sum, 1, 4);
        sum += __shfl_xor_sync(0xffffffffu, sum, 2, 4);
        float lse = m + __logf(sum);
        float2* o = (float2*)(obuf + (long long)v * CC + q * 10);
#pragma unroll
        for (int j = 0; j < 5; j++) o[j] = make_float2(l[2 * j] - lse, l[2 * j + 1] - lse);
    }
}

// ---------------- launch ----------------
extern "C" void kernel_launch(void* const* d_in, const int* in_sizes, int n_in,
                              void* d_out, int out_size) {
    const float* x      = (const float*)d_in[0];
    const float* w_in   = (const float*)d_in[1];
    const float* b_in   = (const float*)d_in[2];
    const float* w_hid  = (const float*)d_in[3];
    const float* b_hid  = (const float*)d_in[4];
    const float* w_out  = (const float*)d_in[5];
    const float* b_out  = (const float*)d_in[6];
    const void*  ei     = d_in[7];
    float* out = (float*)d_out;

    const int TB = 256;
    // preprocessing: dtype detect + zero, degrees, dis, CSR by dst
    detect_zero_k<<<(NN + TB - 1) / TB, TB>>>(ei);
    prep_edges_k<<<(EE / 4 + TB - 1) / TB, TB>>>(ei);
    scan1_k<<<NBLK, 1024>>>();
    scan2_k<<<1, 256>>>();
    scan3_k<<<(NN + TB - 1) / TB, TB>>>();
    fill_k<<<(EE / 4 + TB - 1) / TB, TB>>>();

    // layer 0 GEMM first (128 -> 16): t1 -> bufB  (dir=1 means input is B)
    gemm_in_k<<<NN / 16, 256>>>(x, w_in);

    // agg layers 1..8: fused relu + next-layer 16x16 GEMM
    for (int i = 1; i <= 8; i++) {
        int dir = (i & 1);  // odd: B->A, even: A->B
        const float* Wp = w_hid + (i - 1) * HH * HH;
        const float* Bp = (i == 1) ? b_in : (b_hid + (i - 2) * HH);
        agg_fused_k<0><<<NN / 64, 256>>>(dir, nullptr, Wp, Bp);
    }
    // agg layer 9: relu, t10 = dis*h  (in B, out A)
    agg_fused_k<1><<<NN / 64, 256>>>(1, nullptr, (const float*)nullptr, b_hid + 7 * HH);
    // agg layer 10: gather + W_out + log_softmax  (in A -> d_out)
    agg_fused_k<2><<<NN / 64, 256>>>(0, out, w_out, b_out);
}